// round 15
// baseline (speedup 1.0000x reference)
#include <cuda_runtime.h>
#include <cuda_bf16.h>
#include <cstdint>

#define N_NODES 8192
#define CH      192
#define KNN     8
#define N_ITEMS 288            // 8 groups x 36 upper-triangle tiles
#define N_MUNITS 64            // 8 groups x 8 blocks of 128 rows
#define INFF __int_as_float(0x7f800000)

typedef unsigned long long ull;

// ---------------------------------------------------------------------------
// helpers (baseline PTX only: ldmatrix / mma.sync / cp.async)
// ---------------------------------------------------------------------------
__device__ __forceinline__ uint32_t smem_u32(const void* p) {
    uint32_t a;
    asm("{ .reg .u64 t; cvta.to.shared.u64 t, %1; cvt.u32.u64 %0, t; }"
        : "=r"(a) : "l"(p));
    return a;
}
__device__ __forceinline__ void cpa16(uint32_t dst, const void* src) {
    asm volatile("cp.async.cg.shared.global [%0], [%1], 16;"
                 :: "r"(dst), "l"(src) : "memory");
}
#define CP_COMMIT() asm volatile("cp.async.commit_group;" ::: "memory")
#define CP_WAIT0()  asm volatile("cp.async.wait_group 0;"  ::: "memory")
#define CP_WAIT1()  asm volatile("cp.async.wait_group 1;"  ::: "memory")

#define LDSM_X4(r0, r1, r2, r3, addr) \
    asm volatile("ldmatrix.sync.aligned.m8n8.x4.shared.b16 {%0,%1,%2,%3}, [%4];" \
        : "=r"(r0), "=r"(r1), "=r"(r2), "=r"(r3) : "r"(addr))

#define MMA16816(d, a, b) \
    asm volatile("mma.sync.aligned.m16n8k16.row.col.f32.bf16.bf16.f32 " \
        "{%0,%1,%2,%3}, {%4,%5,%6,%7}, {%8,%9}, {%0,%1,%2,%3};" \
        : "+f"((d)[0]), "+f"((d)[1]), "+f"((d)[2]), "+f"((d)[3]) \
        : "r"((a)[0]), "r"((a)[1]), "r"((a)[2]), "r"((a)[3]), \
          "r"((b)[0]), "r"((b)[1]))

// ---------------------------------------------------------------------------
// scratch (static device globals; no allocations)
// ---------------------------------------------------------------------------
__device__ float g_xf [N_NODES * CH];
__device__ float g_sq [N_NODES];
__device__ float g_dis[N_NODES];
__device__ int   g_nbr[N_NODES * KNN];
__device__ int   g_deg[N_NODES];
__device__ int   g_work;
__device__ int   g_mwork;
__device__ int   g_done[8];
__device__ ull   g_cand[N_NODES * 128];       // 16 lists x 8 per row

__device__ __align__(16) __nv_bfloat16 g_ph [N_NODES * CH];
__device__ __align__(16) __nv_bfloat16 g_pl [N_NODES * CH];
__device__ __align__(16) __nv_bfloat16 g_t1h[N_NODES * CH];
__device__ __align__(16) __nv_bfloat16 g_t1l[N_NODES * CH];
__device__ __align__(16) __nv_bfloat16 g_wh [CH * 384];
__device__ __align__(16) __nv_bfloat16 g_wl [CH * 384];

// ---------------- K1: NCHW -> [N, C] transpose + bf16 hi/lo pack -----------
__global__ void transpose_kernel(const float* __restrict__ x) {
    __shared__ float tile[32][33];
    int b  = blockIdx.z;
    int c0 = blockIdx.y * 32;
    int p0 = blockIdx.x * 32;
    int tx = threadIdx.x, ty = threadIdx.y;
    tile[ty][tx] = x[((b * CH) + (c0 + ty)) * 1024 + p0 + tx];
    __syncthreads();
    float v   = tile[tx][ty];
    int node  = b * 1024 + p0 + ty;
    int c     = c0 + tx;
    g_xf[node * CH + c] = v;
    __nv_bfloat16 h = __float2bfloat16(v);
    g_ph[node * CH + c] = h;
    g_pl[node * CH + c] = __float2bfloat16(v - __bfloat162float(h));
}

// ---------------- K2: squared norms + zero degree + counter resets ----------
__global__ void sqdeg_kernel() {
    if (blockIdx.x == 0) {
        if (threadIdx.x == 0) { g_work = 0; g_mwork = 0; }
        if (threadIdx.x < 8)  g_done[threadIdx.x] = 0;
    }
    int q    = blockIdx.x * 8 + (threadIdx.x >> 5);
    int lane = threadIdx.x & 31;
    const float* row = g_xf + q * CH;
    float s = 0.f;
    #pragma unroll
    for (int c = lane; c < CH; c += 32) { float v = row[c]; s += v * v; }
    #pragma unroll
    for (int o = 16; o; o >>= 1) s += __shfl_xor_sync(0xffffffffu, s, o);
    if (lane == 0) { g_sq[q] = s; g_deg[q] = 0; }
}

// ---------------- K2c: pack W transposed (coalesced): g_w*[n][k] ------------
__global__ void packw_kernel(const float* __restrict__ W0,
                             const float* __restrict__ W1) {
    __shared__ float t[32][33];
    int n0 = blockIdx.x * 32;
    int k0 = blockIdx.y * 32;
    int tx = threadIdx.x, ty = threadIdx.y;
    int k  = k0 + ty, n = n0 + tx;
    t[ty][tx] = (k < CH) ? W0[k * CH + n] : W1[(k - CH) * CH + n];
    __syncthreads();
    float v = t[tx][ty];
    __nv_bfloat16 h = __float2bfloat16(v);
    g_wh[(n0 + ty) * 384 + k0 + tx] = h;
    g_wl[(n0 + ty) * 384 + k0 + tx] = __float2bfloat16(v - __bfloat162float(h));
}

// ---------------- K3: persistent fused HMMA d2 + top-8 + inline merge -------
#define OFF_MISC 0
#define OFF_SQ   128                         // sqs[2][1024]
#define OFF_D2   (OFF_SQ + 8192)             // 128 x 129 floats
#define OFF_STG  (OFF_D2 + 66048)
#define STG_SZ   40960                       // Ah|Al|Bh|Bl, 128 rows x 80B each
#define SMEM_TOTAL (OFF_STG + 3 * STG_SZ)    // 197248

__device__ __forceinline__ void decode_item(int w, int& g, int& I, int& J) {
    g = w / 36;
    int r = w - g * 36;
    int i = 0, span = 8;
    while (r >= span) { r -= span; span--; i++; }
    I = i; J = i + r;
}

__device__ __forceinline__ void load_chunk(uint32_t stage, int Arow0, int Brow0,
                                           int k0, int tid) {
    #pragma unroll
    for (int i = 0; i < 4; i++) {
        int p   = tid + i * 512;
        int mat = p >> 9;                    // 0:Ah 1:Al 2:Bh 3:Bl
        int row = (p >> 2) & 127;
        int kq  = p & 3;
        const __nv_bfloat16* base = (mat & 1) ? g_pl : g_ph;
        int node = ((mat < 2) ? Arow0 : Brow0) + row;
        cpa16(stage + mat * 10240 + row * 80 + kq * 16,
              base + node * CH + k0 + kq * 8);
    }
}

__device__ __forceinline__ void top8_insert(float d2, int n, float* v, int* id8) {
    if (d2 < v[7]) {
        v[7] = d2; id8[7] = n;
        #pragma unroll
        for (int s = 7; s > 0; s--) {
            if (v[s] < v[s - 1]) {
                float tv = v[s]; v[s] = v[s - 1]; v[s - 1] = tv;
                int   ti = id8[s]; id8[s] = id8[s - 1]; id8[s - 1] = ti;
            }
        }
    }
}

// exact R6 merge body for one row q (whole warp participates)
__device__ __forceinline__ void merge_row(int q, int lane) {
    if (q == N_NODES - 1) {                  // warp-uniform branch: safe
        if (lane < KNN) g_nbr[q * KNN + lane] = 0;
        return;
    }
    const ull* cd = g_cand + (size_t)q * 128;
    ull k0 = cd[lane], k1 = cd[32 + lane],
        k2 = cd[64 + lane], k3 = cd[96 + lane];
    #define CSWP(a, b) if (b < a) { ull t = a; a = b; b = t; }
    CSWP(k0, k1); CSWP(k2, k3); CSWP(k0, k2); CSWP(k1, k3); CSWP(k1, k2);
    #undef CSWP
    #pragma unroll
    for (int r = 0; r < KNN; r++) {
        ull m = k0;
        #pragma unroll
        for (int o = 16; o; o >>= 1) {
            ull other = __shfl_xor_sync(0xffffffffu, m, o);
            m = (other < m) ? other : m;
        }
        if (k0 == m) {
            int nb = (int)(m & 0xffffffffu);
            g_nbr[q * KNN + r] = nb;
            atomicAdd(&g_deg[nb], 1);
            k0 = k1; k1 = k2; k2 = k3; k3 = 0xFFFFFFFFFFFFFFFFull;
        }
    }
}

__global__ __launch_bounds__(512, 1) void knn_kernel() {
    extern __shared__ char smem[];
    uint32_t sb = smem_u32(smem);
    int*   misc = (int*)smem;
    float* sqsA = (float*)(smem + OFF_SQ);
    float* d2s  = (float*)(smem + OFF_D2);

    int tid = threadIdx.x, lane = tid & 31, wid = tid >> 5;
    int wm = wid >> 2, wn = wid & 3;        // 4 x 4 warp grid, 32x32 per warp

    if (tid == 0) misc[0] = atomicAdd(&g_work, 1);
    __syncthreads();
    int w = misc[0];
    int g, I, J;
    decode_item(w, g, I, J);
    int gStart = g << 10;
    int gSize  = (g == 7) ? 1023 : 1024;
    int A0 = gStart + I * 128, B0 = gStart + J * 128;
    int sqbuf = 0;

    if (w < N_ITEMS) {
        for (int i = tid; i < 1024; i += 512) sqsA[i] = g_sq[gStart + i];
        load_chunk(sb + OFF_STG, A0, B0, 0, tid);  CP_COMMIT();
        load_chunk(sb + OFF_STG + STG_SZ, A0, B0, 32, tid);  CP_COMMIT();
    }
    __syncthreads();

    while (w < N_ITEMS) {
        float* sqs = sqsA + sqbuf * 1024;
        float acc[8][4];
        #pragma unroll
        for (int i = 0; i < 8; i++)
            #pragma unroll
            for (int j = 0; j < 4; j++) acc[i][j] = 0.f;

        int wNext = 0x7fffffff;
        int gN = 0, IN_ = 0, JN = 0, A0n = 0, B0n = 0, gStartN = 0;

        for (int c = 0; c < 6; c++) {
            if (c == 5 && wNext >= N_ITEMS) { CP_WAIT0(); } else { CP_WAIT1(); }
            __syncthreads();
            if (c <= 3) {
                load_chunk(sb + OFF_STG + ((c + 2) % 3) * STG_SZ, A0, B0,
                           (c + 2) * 32, tid);
                CP_COMMIT();
            }
            if (c == 3 && tid == 0) misc[1] = atomicAdd(&g_work, 1);
            if (c == 4) {
                wNext = misc[1];
                if (wNext < N_ITEMS) {
                    decode_item(wNext, gN, IN_, JN);
                    gStartN = gN << 10;
                    A0n = gStartN + IN_ * 128; B0n = gStartN + JN * 128;
                    load_chunk(sb + OFF_STG, A0n, B0n, 0, tid);
                    CP_COMMIT();
                }
            }
            uint32_t st = sb + OFF_STG + (c % 3) * STG_SZ;
            #pragma unroll
            for (int pass = 0; pass < 3; pass++) {
                uint32_t Ab = st + (pass == 2 ? 10240u : 0u);
                uint32_t Bb = st + (pass == 1 ? 30720u : 20480u);
                #pragma unroll
                for (int ks = 0; ks < 32; ks += 16) {
                    uint32_t a[2][4];
                    #pragma unroll
                    for (int mt = 0; mt < 2; mt++) {
                        uint32_t addr = Ab + (wm * 32 + mt * 16 + (lane & 15)) * 80
                                      + (ks + ((lane >> 4) << 3)) * 2;
                        LDSM_X4(a[mt][0], a[mt][1], a[mt][2], a[mt][3], addr);
                    }
                    uint32_t b[4][2];
                    #pragma unroll
                    for (int nt2 = 0; nt2 < 2; nt2++) {
                        int qq = lane >> 3, r = lane & 7;
                        uint32_t addr = Bb
                            + (wn * 32 + nt2 * 16 + ((qq >> 1) << 3) + r) * 80
                            + (ks + ((qq & 1) << 3)) * 2;
                        LDSM_X4(b[nt2 * 2][0], b[nt2 * 2][1],
                                b[nt2 * 2 + 1][0], b[nt2 * 2 + 1][1], addr);
                    }
                    #pragma unroll
                    for (int mt = 0; mt < 2; mt++)
                        #pragma unroll
                        for (int nt = 0; nt < 4; nt++)
                            MMA16816(acc[mt * 4 + nt], a[mt], b[nt]);
                }
            }
        }

        // epilogue: dot -> smem tile
        #pragma unroll
        for (int mt = 0; mt < 2; mt++)
            #pragma unroll
            for (int nt = 0; nt < 4; nt++) {
                int r0 = wm * 32 + mt * 16 + (lane >> 2);
                int c0 = wn * 32 + nt * 8 + (lane & 3) * 2;
                float* p = d2s + r0 * 129 + c0;
                p[0]           = acc[mt * 4 + nt][0];
                p[1]           = acc[mt * 4 + nt][1];
                p[129 * 8]     = acc[mt * 4 + nt][2];
                p[129 * 8 + 1] = acc[mt * 4 + nt][3];
            }
        bool hasNext = (wNext < N_ITEMS);
        if (hasNext) {
            load_chunk(sb + OFF_STG + STG_SZ, A0n, B0n, 32, tid);
            if (tid < 256)
                cpa16(sb + OFF_SQ + (sqbuf ^ 1) * 4096 + tid * 16,
                      g_sq + gStartN + tid * 4);
            CP_COMMIT();
        }
        __syncthreads();

        // scans run CONCURRENTLY: threads 0-255 row scan, 256-511 col scan
        if (tid < 256) {
            int   row  = tid & 127;
            int   half = tid >> 7;
            int   mLoc = I * 128 + row;
            float sqm  = sqs[mLoc];
            float v[8]; int id8[8];
            #pragma unroll
            for (int s = 0; s < 8; s++) { v[s] = INFF; id8[s] = 1 << 30; }
            const float* rp = d2s + row * 129 + half * 64;
            int nb0 = J * 128 + half * 64;
            #pragma unroll 4
            for (int c = 0; c < 64; c++) {
                int   n   = nb0 + c;
                float d2  = fmaxf(fmaf(-2.f, rp[c], sqm + sqs[n]), 0.f);
                bool  ok  = (n < gSize) && (n != mLoc);
                if (ok) top8_insert(d2, n, v, id8);
            }
            int q = gStart + mLoc;
            ull* cd = g_cand + (size_t)q * 128 + J * 16 + half * 8;
            #pragma unroll
            for (int r = 0; r < KNN; r++)
                cd[r] = ((ull)__float_as_uint(v[r]) << 32)
                      | (unsigned)(gStart + id8[r]);
        } else if (I != J) {
            int   t2   = tid - 256;
            int   row  = t2 & 127;
            int   half = t2 >> 7;
            int   nLoc = J * 128 + row;
            float sqn  = sqs[nLoc];
            float v[8]; int id8[8];
            #pragma unroll
            for (int s = 0; s < 8; s++) { v[s] = INFF; id8[s] = 1 << 30; }
            int mb0 = I * 128 + half * 64;
            const float* cp = d2s + (half * 64) * 129 + row;
            #pragma unroll 4
            for (int c = 0; c < 64; c++) {
                int   m   = mb0 + c;
                float d2  = fmaxf(fmaf(-2.f, cp[c * 129], sqn + sqs[m]), 0.f);
                if (m < gSize) top8_insert(d2, m, v, id8);
            }
            int q = gStart + nLoc;
            ull* cd = g_cand + (size_t)q * 128 + I * 16 + half * 8;
            #pragma unroll
            for (int r = 0; r < KNN; r++)
                cd[r] = ((ull)__float_as_uint(v[r]) << 32)
                      | (unsigned)(gStart + id8[r]);
        }
        // release: make this item's candidates visible, then count it done
        __threadfence();
        __syncthreads();
        if (tid == 0) atomicAdd(&g_done[gStart >> 10], 1);

        w = wNext; g = gN; I = IN_; J = JN;
        gStart = gStartN; gSize = (g == 7) ? 1023 : 1024;
        A0 = A0n; B0 = B0n; sqbuf ^= 1;
    }

    // ---------------- inline merge phase (persistent tail) ------------------
    for (;;) {
        if (tid == 0) misc[2] = atomicAdd(&g_mwork, 1);
        __syncthreads();
        int u = misc[2];
        __syncthreads();                      // protect misc[2] before next pop
        if (u >= N_MUNITS) break;
        int mg = u >> 3;
        if (tid == 0) {
            while (atomicAdd(&g_done[mg], 0) < 36) { }   // spin until group ready
        }
        __syncthreads();
        __threadfence();                      // acquire: candidates visible
        int qbase = mg * 1024 + (u & 7) * 128;
        #pragma unroll
        for (int r = 0; r < 8; r++)
            merge_row(qbase + wid * 8 + r, lane);
    }
}

// ---------------- K5: dis = deg^{-1/2} --------------------------------------
__global__ void dis_kernel() {
    int i = blockIdx.x * 256 + threadIdx.x;
    if (i < N_NODES) {
        int d = g_deg[i];
        g_dis[i] = (d > 0) ? rsqrtf((float)d) : 0.0f;
    }
}

// ---------------- K6: Tx1 -> bf16 hi/lo --------------------------------------
__global__ void tx1_kernel() {
    int q = blockIdx.x;
    int c = threadIdx.x;
    float dq = g_dis[q];
    float s = 0.f;
    #pragma unroll
    for (int e = 0; e < KNN; e++) {
        int j = g_nbr[q * KNN + e];
        s += g_dis[j] * g_xf[j * CH + c];
    }
    float t1 = -dq * s;
    __nv_bfloat16 h = __float2bfloat16(t1);
    g_t1h[q * CH + c] = h;
    g_t1l[q * CH + c] = __float2bfloat16(t1 - __bfloat162float(h));
}

// ---------------- K7: HMMA out = [xf|tx1] @ [W0;W1] + bias -------------------
#define OSTG 40960
#define OSMEM (2 * OSTG + 768)

__device__ __forceinline__ void load_chunk_o(uint32_t stage, int m0, int c, int tid) {
    int k0 = (c < 6 ? c : c - 6) * 32;
    const __nv_bfloat16* ah = (c < 6) ? g_ph : g_t1h;
    const __nv_bfloat16* al = (c < 6) ? g_pl : g_t1l;
    {
        int p   = tid;
        int mat = p >> 8;
        int row = (p >> 2) & 63;
        int kq  = p & 3;
        cpa16(stage + mat * 5120 + row * 80 + kq * 16,
              (mat ? al : ah) + (m0 + row) * CH + k0 + kq * 8);
    }
    #pragma unroll
    for (int i = 0; i < 3; i++) {
        int pb  = tid + i * 512;
        int mat = pb >= 768;
        int row = (pb >> 2) % 192;
        int kq  = pb & 3;
        cpa16(stage + 10240 + mat * 15360 + row * 80 + kq * 16,
              (mat ? g_wl : g_wh) + row * 384 + c * 32 + kq * 8);
    }
}

__global__ __launch_bounds__(512, 1) void out_hmma_kernel(
    const float* __restrict__ bias, float* __restrict__ out)
{
    extern __shared__ char smem[];
    uint32_t sb = smem_u32(smem);
    float* bs = (float*)(smem + 2 * OSTG);

    int tid = threadIdx.x, lane = tid & 31, wid = tid >> 5;
    int wm = wid >> 2, wn = wid & 3;
    int m0 = blockIdx.x * 64;

    if (tid < CH) bs[tid] = bias[tid];

    float acc[6][4];
    #pragma unroll
    for (int i = 0; i < 6; i++)
        #pragma unroll
        for (int j = 0; j < 4; j++) acc[i][j] = 0.f;

    load_chunk_o(sb, m0, 0, tid);
    CP_COMMIT();

    for (int c = 0; c < 12; c++) {
        CP_WAIT0();
        __syncthreads();
        if (c < 11) {
            load_chunk_o(sb + ((c + 1) & 1) * OSTG, m0, c + 1, tid);
            CP_COMMIT();
        }
        uint32_t st = sb + (c & 1) * OSTG;
        #pragma unroll
        for (int pass = 0; pass < 3; pass++) {
            uint32_t Ab = st + (pass == 2 ? 5120u : 0u);
            uint32_t Bb = st + (pass == 1 ? 25600u : 10240u);
            #pragma unroll
            for (int ks = 0; ks < 32; ks += 16) {
                uint32_t a[4];
                {
                    uint32_t addr = Ab + (wm * 16 + (lane & 15)) * 80
                                  + (ks + ((lane >> 4) << 3)) * 2;
                    LDSM_X4(a[0], a[1], a[2], a[3], addr);
                }
                uint32_t b[6][2];
                #pragma unroll
                for (int nt2 = 0; nt2 < 3; nt2++) {
                    int qq = lane >> 3, r = lane & 7;
                    uint32_t addr = Bb
                        + (wn * 48 + nt2 * 16 + ((qq >> 1) << 3) + r) * 80
                        + (ks + ((qq & 1) << 3)) * 2;
                    LDSM_X4(b[nt2 * 2][0], b[nt2 * 2][1],
                            b[nt2 * 2 + 1][0], b[nt2 * 2 + 1][1], addr);
                }
                #pragma unroll
                for (int nt = 0; nt < 6; nt++)
                    MMA16816(acc[nt], a, b[nt]);
            }
        }
    }

    #pragma unroll
    for (int nt = 0; nt < 6; nt++) {
        int r  = m0 + wm * 16 + (lane >> 2);
        int cc = wn * 48 + nt * 8 + (lane & 3) * 2;
        float b0 = bs[cc], b1 = bs[cc + 1];
        out[r * CH + cc]           = acc[nt][0] + b0;
        out[r * CH + cc + 1]       = acc[nt][1] + b1;
        out[(r + 8) * CH + cc]     = acc[nt][2] + b0;
        out[(r + 8) * CH + cc + 1] = acc[nt][3] + b1;
    }
}

// ---------------- launch -----------------------------------------------------
extern "C" void kernel_launch(void* const* d_in, const int* in_sizes, int n_in,
                              void* d_out, int out_size) {
    const float* x    = (const float*)d_in[0];
    const float* W0   = (const float*)d_in[1];
    const float* W1   = (const float*)d_in[2];
    const float* bias = (const float*)d_in[3];
    float* out = (float*)d_out;

    static int smem_set = 0;
    if (!smem_set) {
        cudaFuncSetAttribute(knn_kernel,
                             cudaFuncAttributeMaxDynamicSharedMemorySize,
                             SMEM_TOTAL);
        cudaFuncSetAttribute(out_hmma_kernel,
                             cudaFuncAttributeMaxDynamicSharedMemorySize,
                             OSMEM);
        smem_set = 1;
    }

    transpose_kernel<<<dim3(32, 6, 8), dim3(32, 32)>>>(x);
    sqdeg_kernel<<<1024, 256>>>();
    packw_kernel<<<dim3(6, 12), dim3(32, 32)>>>(W0, W1);
    knn_kernel<<<152, 512, SMEM_TOTAL>>>();
    dis_kernel<<<32, 256>>>();
    tx1_kernel<<<8192, 192>>>();
    out_hmma_kernel<<<128, 512, OSMEM>>>(bias, out);
}

// round 16
// speedup vs baseline: 1.1838x; 1.1838x over previous
#include <cuda_runtime.h>
#include <cuda_bf16.h>
#include <cstdint>

#define N_NODES 8192
#define CH      192
#define KNN     8
#define N_ITEMS 288            // 8 groups x 36 upper-triangle tiles
#define INFF __int_as_float(0x7f800000)

typedef unsigned long long ull;

// ---------------------------------------------------------------------------
// helpers (baseline PTX only: ldmatrix / mma.sync / cp.async)
// ---------------------------------------------------------------------------
__device__ __forceinline__ uint32_t smem_u32(const void* p) {
    uint32_t a;
    asm("{ .reg .u64 t; cvta.to.shared.u64 t, %1; cvt.u32.u64 %0, t; }"
        : "=r"(a) : "l"(p));
    return a;
}
__device__ __forceinline__ void cpa16(uint32_t dst, const void* src) {
    asm volatile("cp.async.cg.shared.global [%0], [%1], 16;"
                 :: "r"(dst), "l"(src) : "memory");
}
#define CP_COMMIT() asm volatile("cp.async.commit_group;" ::: "memory")
#define CP_WAIT0()  asm volatile("cp.async.wait_group 0;"  ::: "memory")
#define CP_WAIT1()  asm volatile("cp.async.wait_group 1;"  ::: "memory")

#define LDSM_X4(r0, r1, r2, r3, addr) \
    asm volatile("ldmatrix.sync.aligned.m8n8.x4.shared.b16 {%0,%1,%2,%3}, [%4];" \
        : "=r"(r0), "=r"(r1), "=r"(r2), "=r"(r3) : "r"(addr))

#define MMA16816(d, a, b) \
    asm volatile("mma.sync.aligned.m16n8k16.row.col.f32.bf16.bf16.f32 " \
        "{%0,%1,%2,%3}, {%4,%5,%6,%7}, {%8,%9}, {%0,%1,%2,%3};" \
        : "+f"((d)[0]), "+f"((d)[1]), "+f"((d)[2]), "+f"((d)[3]) \
        : "r"((a)[0]), "r"((a)[1]), "r"((a)[2]), "r"((a)[3]), \
          "r"((b)[0]), "r"((b)[1]))

// ---------------------------------------------------------------------------
// scratch (static device globals; no allocations)
// ---------------------------------------------------------------------------
__device__ float g_xf [N_NODES * CH];
__device__ float g_sq [N_NODES];
__device__ float g_dis[N_NODES];
__device__ int   g_nbr[N_NODES * KNN];
__device__ int   g_deg[N_NODES];
__device__ int   g_work;
__device__ ull   g_cand[N_NODES * 128];       // 16 lists x 8 per row

__device__ __align__(16) __nv_bfloat16 g_ph [N_NODES * CH];
__device__ __align__(16) __nv_bfloat16 g_pl [N_NODES * CH];
__device__ __align__(16) __nv_bfloat16 g_t1h[N_NODES * CH];
__device__ __align__(16) __nv_bfloat16 g_t1l[N_NODES * CH];
__device__ __align__(16) __nv_bfloat16 g_wh [CH * 384];
__device__ __align__(16) __nv_bfloat16 g_wl [CH * 384];

// ---------------- K1: NCHW -> [N, C] transpose + bf16 hi/lo pack -----------
__global__ void transpose_kernel(const float* __restrict__ x) {
    __shared__ float tile[32][33];
    int b  = blockIdx.z;
    int c0 = blockIdx.y * 32;
    int p0 = blockIdx.x * 32;
    int tx = threadIdx.x, ty = threadIdx.y;
    tile[ty][tx] = x[((b * CH) + (c0 + ty)) * 1024 + p0 + tx];
    __syncthreads();
    float v   = tile[tx][ty];
    int node  = b * 1024 + p0 + ty;
    int c     = c0 + tx;
    g_xf[node * CH + c] = v;
    __nv_bfloat16 h = __float2bfloat16(v);
    g_ph[node * CH + c] = h;
    g_pl[node * CH + c] = __float2bfloat16(v - __bfloat162float(h));
}

// ---------------- K2: squared norms + zero degree + work-counter reset ------
__global__ void sqdeg_kernel() {
    if (blockIdx.x == 0 && threadIdx.x == 0) g_work = 0;
    int q    = blockIdx.x * 8 + (threadIdx.x >> 5);
    int lane = threadIdx.x & 31;
    const float* row = g_xf + q * CH;
    float s = 0.f;
    #pragma unroll
    for (int c = lane; c < CH; c += 32) { float v = row[c]; s += v * v; }
    #pragma unroll
    for (int o = 16; o; o >>= 1) s += __shfl_xor_sync(0xffffffffu, s, o);
    if (lane == 0) { g_sq[q] = s; g_deg[q] = 0; }
}

// ---------------- K2c: pack W transposed (coalesced): g_w*[n][k] ------------
__global__ void packw_kernel(const float* __restrict__ W0,
                             const float* __restrict__ W1) {
    __shared__ float t[32][33];
    int n0 = blockIdx.x * 32;
    int k0 = blockIdx.y * 32;
    int tx = threadIdx.x, ty = threadIdx.y;
    int k  = k0 + ty, n = n0 + tx;
    t[ty][tx] = (k < CH) ? W0[k * CH + n] : W1[(k - CH) * CH + n];
    __syncthreads();
    float v = t[tx][ty];
    __nv_bfloat16 h = __float2bfloat16(v);
    g_wh[(n0 + ty) * 384 + k0 + tx] = h;
    g_wl[(n0 + ty) * 384 + k0 + tx] = __float2bfloat16(v - __bfloat162float(h));
}

// ---------------- K3: persistent fused HMMA d2 + symmetric top-8 (R6) ------
#define OFF_MISC 0
#define OFF_SQ   128                         // sqs[2][1024]
#define OFF_D2   (OFF_SQ + 8192)             // 128 x 129 floats
#define OFF_STG  (OFF_D2 + 66048)
#define STG_SZ   40960                       // Ah|Al|Bh|Bl, 128 rows x 80B each
#define SMEM_TOTAL (OFF_STG + 3 * STG_SZ)    // 197248

__device__ __forceinline__ void decode_item(int w, int& g, int& I, int& J) {
    g = w / 36;
    int r = w - g * 36;
    int i = 0, span = 8;
    while (r >= span) { r -= span; span--; i++; }
    I = i; J = i + r;
}

__device__ __forceinline__ void load_chunk(uint32_t stage, int Arow0, int Brow0,
                                           int k0, int tid) {
    #pragma unroll
    for (int i = 0; i < 4; i++) {
        int p   = tid + i * 512;
        int mat = p >> 9;                    // 0:Ah 1:Al 2:Bh 3:Bl
        int row = (p >> 2) & 127;
        int kq  = p & 3;
        const __nv_bfloat16* base = (mat & 1) ? g_pl : g_ph;
        int node = ((mat < 2) ? Arow0 : Brow0) + row;
        cpa16(stage + mat * 10240 + row * 80 + kq * 16,
              base + node * CH + k0 + kq * 8);
    }
}

__device__ __forceinline__ void top8_insert(float d2, int n, float* v, int* id8) {
    if (d2 < v[7]) {
        v[7] = d2; id8[7] = n;
        #pragma unroll
        for (int s = 7; s > 0; s--) {
            if (v[s] < v[s - 1]) {
                float tv = v[s]; v[s] = v[s - 1]; v[s - 1] = tv;
                int   ti = id8[s]; id8[s] = id8[s - 1]; id8[s - 1] = ti;
            }
        }
    }
}

__global__ __launch_bounds__(512, 1) void knn_kernel() {
    extern __shared__ char smem[];
    uint32_t sb = smem_u32(smem);
    int*   misc = (int*)smem;
    float* sqsA = (float*)(smem + OFF_SQ);
    float* d2s  = (float*)(smem + OFF_D2);

    int tid = threadIdx.x, lane = tid & 31, wid = tid >> 5;
    int wm = wid >> 2, wn = wid & 3;        // 4 x 4 warp grid, 32x32 per warp

    if (tid == 0) misc[0] = atomicAdd(&g_work, 1);
    __syncthreads();
    int w = misc[0];
    int g, I, J;
    decode_item(w, g, I, J);
    int gStart = g << 10;
    int gSize  = (g == 7) ? 1023 : 1024;
    int A0 = gStart + I * 128, B0 = gStart + J * 128;
    int sqbuf = 0;

    for (int i = tid; i < 1024; i += 512) sqsA[i] = g_sq[gStart + i];
    load_chunk(sb + OFF_STG, A0, B0, 0, tid);  CP_COMMIT();
    load_chunk(sb + OFF_STG + STG_SZ, A0, B0, 32, tid);  CP_COMMIT();
    __syncthreads();

    while (w < N_ITEMS) {
        float* sqs = sqsA + sqbuf * 1024;
        float acc[8][4];
        #pragma unroll
        for (int i = 0; i < 8; i++)
            #pragma unroll
            for (int j = 0; j < 4; j++) acc[i][j] = 0.f;

        int wNext = 0x7fffffff;
        int gN = 0, IN_ = 0, JN = 0, A0n = 0, B0n = 0, gStartN = 0;

        for (int c = 0; c < 6; c++) {
            if (c == 5 && wNext >= N_ITEMS) { CP_WAIT0(); } else { CP_WAIT1(); }
            __syncthreads();
            if (c <= 3) {
                load_chunk(sb + OFF_STG + ((c + 2) % 3) * STG_SZ, A0, B0,
                           (c + 2) * 32, tid);
                CP_COMMIT();
            }
            if (c == 3 && tid == 0) misc[1] = atomicAdd(&g_work, 1);
            if (c == 4) {
                wNext = misc[1];
                if (wNext < N_ITEMS) {
                    decode_item(wNext, gN, IN_, JN);
                    gStartN = gN << 10;
                    A0n = gStartN + IN_ * 128; B0n = gStartN + JN * 128;
                    load_chunk(sb + OFF_STG, A0n, B0n, 0, tid);
                    CP_COMMIT();
                }
            }
            uint32_t st = sb + OFF_STG + (c % 3) * STG_SZ;
            #pragma unroll
            for (int pass = 0; pass < 3; pass++) {
                uint32_t Ab = st + (pass == 2 ? 10240u : 0u);
                uint32_t Bb = st + (pass == 1 ? 30720u : 20480u);
                #pragma unroll
                for (int ks = 0; ks < 32; ks += 16) {
                    uint32_t a[2][4];
                    #pragma unroll
                    for (int mt = 0; mt < 2; mt++) {
                        uint32_t addr = Ab + (wm * 32 + mt * 16 + (lane & 15)) * 80
                                      + (ks + ((lane >> 4) << 3)) * 2;
                        LDSM_X4(a[mt][0], a[mt][1], a[mt][2], a[mt][3], addr);
                    }
                    uint32_t b[4][2];
                    #pragma unroll
                    for (int nt2 = 0; nt2 < 2; nt2++) {
                        int qq = lane >> 3, r = lane & 7;
                        uint32_t addr = Bb
                            + (wn * 32 + nt2 * 16 + ((qq >> 1) << 3) + r) * 80
                            + (ks + ((qq & 1) << 3)) * 2;
                        LDSM_X4(b[nt2 * 2][0], b[nt2 * 2][1],
                                b[nt2 * 2 + 1][0], b[nt2 * 2 + 1][1], addr);
                    }
                    #pragma unroll
                    for (int mt = 0; mt < 2; mt++)
                        #pragma unroll
                        for (int nt = 0; nt < 4; nt++)
                            MMA16816(acc[mt * 4 + nt], a[mt], b[nt]);
                }
            }
        }

        // epilogue: dot -> smem tile
        #pragma unroll
        for (int mt = 0; mt < 2; mt++)
            #pragma unroll
            for (int nt = 0; nt < 4; nt++) {
                int r0 = wm * 32 + mt * 16 + (lane >> 2);
                int c0 = wn * 32 + nt * 8 + (lane & 3) * 2;
                float* p = d2s + r0 * 129 + c0;
                p[0]           = acc[mt * 4 + nt][0];
                p[1]           = acc[mt * 4 + nt][1];
                p[129 * 8]     = acc[mt * 4 + nt][2];
                p[129 * 8 + 1] = acc[mt * 4 + nt][3];
            }
        bool hasNext = (wNext < N_ITEMS);
        if (hasNext) {
            load_chunk(sb + OFF_STG + STG_SZ, A0n, B0n, 32, tid);
            if (tid < 256)
                cpa16(sb + OFF_SQ + (sqbuf ^ 1) * 4096 + tid * 16,
                      g_sq + gStartN + tid * 4);
            CP_COMMIT();
        }
        __syncthreads();

        // scans run CONCURRENTLY: threads 0-255 row scan, 256-511 col scan
        if (tid < 256) {
            int   row  = tid & 127;
            int   half = tid >> 7;
            int   mLoc = I * 128 + row;
            float sqm  = sqs[mLoc];
            float v[8]; int id8[8];
            #pragma unroll
            for (int s = 0; s < 8; s++) { v[s] = INFF; id8[s] = 1 << 30; }
            const float* rp = d2s + row * 129 + half * 64;
            int nb0 = J * 128 + half * 64;
            #pragma unroll 4
            for (int c = 0; c < 64; c++) {
                int   n   = nb0 + c;
                float d2  = fmaxf(fmaf(-2.f, rp[c], sqm + sqs[n]), 0.f);
                bool  ok  = (n < gSize) && (n != mLoc);
                if (ok) top8_insert(d2, n, v, id8);
            }
            int q = gStart + mLoc;
            ull* cd = g_cand + (size_t)q * 128 + J * 16 + half * 8;
            #pragma unroll
            for (int r = 0; r < KNN; r++)
                cd[r] = ((ull)__float_as_uint(v[r]) << 32)
                      | (unsigned)(gStart + id8[r]);
        } else if (I != J) {
            int   t2   = tid - 256;
            int   row  = t2 & 127;
            int   half = t2 >> 7;
            int   nLoc = J * 128 + row;
            float sqn  = sqs[nLoc];
            float v[8]; int id8[8];
            #pragma unroll
            for (int s = 0; s < 8; s++) { v[s] = INFF; id8[s] = 1 << 30; }
            int mb0 = I * 128 + half * 64;
            const float* cp = d2s + (half * 64) * 129 + row;
            #pragma unroll 4
            for (int c = 0; c < 64; c++) {
                int   m   = mb0 + c;
                float d2  = fmaxf(fmaf(-2.f, cp[c * 129], sqn + sqs[m]), 0.f);
                if (m < gSize) top8_insert(d2, m, v, id8);
            }
            int q = gStart + nLoc;
            ull* cd = g_cand + (size_t)q * 128 + I * 16 + half * 8;
            #pragma unroll
            for (int r = 0; r < KNN; r++)
                cd[r] = ((ull)__float_as_uint(v[r]) << 32)
                      | (unsigned)(gStart + id8[r]);
        }
        __syncthreads();

        w = wNext; g = gN; I = IN_; J = JN;
        gStart = gStartN; gSize = (g == 7) ? 1023 : 1024;
        A0 = A0n; B0 = B0n; sqbuf ^= 1;
    }
}

// ---------------- K4: 4-rows-per-warp merge, MLP=16 front-batched loads -----
__global__ void merge_kernel() {
    int tid  = threadIdx.x;
    int lane = tid & 31, wid = tid >> 5;
    int q0   = (blockIdx.x * 8 + wid) * 4;    // 4 rows per warp

    // front-batch ALL 16 loads per lane (independent -> 16 outstanding LDGs)
    ull k[4][4];
    #pragma unroll
    for (int r = 0; r < 4; r++) {
        const ull* cd = g_cand + (size_t)(q0 + r) * 128;
        #pragma unroll
        for (int i = 0; i < 4; i++)
            k[r][i] = __ldg(cd + i * 32 + lane);
    }

    // process each row (row loop warp-uniform; collectives safe)
    #pragma unroll
    for (int r = 0; r < 4; r++) {
        int q = q0 + r;
        if (q == N_NODES - 1) {               // warp-uniform branch
            if (lane < KNN) g_nbr[q * KNN + lane] = 0;
            continue;
        }
        ull k0 = k[r][0], k1 = k[r][1], k2 = k[r][2], k3 = k[r][3];
        #define CSWP(a, b) if (b < a) { ull t = a; a = b; b = t; }
        CSWP(k0, k1); CSWP(k2, k3); CSWP(k0, k2); CSWP(k1, k3); CSWP(k1, k2);
        #undef CSWP

        #pragma unroll
        for (int rr = 0; rr < KNN; rr++) {
            ull m = k0;
            #pragma unroll
            for (int o = 16; o; o >>= 1) {
                ull other = __shfl_xor_sync(0xffffffffu, m, o);
                m = (other < m) ? other : m;
            }
            if (k0 == m) {                    // unique owner (idx unique)
                int nb = (int)(m & 0xffffffffu);
                g_nbr[q * KNN + rr] = nb;
                atomicAdd(&g_deg[nb], 1);
                k0 = k1; k1 = k2; k2 = k3; k3 = 0xFFFFFFFFFFFFFFFFull;
            }
        }
    }
}

// ---------------- K5: dis = deg^{-1/2} --------------------------------------
__global__ void dis_kernel() {
    int i = blockIdx.x * 256 + threadIdx.x;
    if (i < N_NODES) {
        int d = g_deg[i];
        g_dis[i] = (d > 0) ? rsqrtf((float)d) : 0.0f;
    }
}

// ---------------- K6: Tx1 -> bf16 hi/lo --------------------------------------
__global__ void tx1_kernel() {
    int q = blockIdx.x;
    int c = threadIdx.x;
    float dq = g_dis[q];
    float s = 0.f;
    #pragma unroll
    for (int e = 0; e < KNN; e++) {
        int j = g_nbr[q * KNN + e];
        s += g_dis[j] * g_xf[j * CH + c];
    }
    float t1 = -dq * s;
    __nv_bfloat16 h = __float2bfloat16(t1);
    g_t1h[q * CH + c] = h;
    g_t1l[q * CH + c] = __float2bfloat16(t1 - __bfloat162float(h));
}

// ---------------- K7: HMMA out = [xf|tx1] @ [W0;W1] + bias -------------------
#define OSTG 40960
#define OSMEM (2 * OSTG + 768)

__device__ __forceinline__ void load_chunk_o(uint32_t stage, int m0, int c, int tid) {
    int k0 = (c < 6 ? c : c - 6) * 32;
    const __nv_bfloat16* ah = (c < 6) ? g_ph : g_t1h;
    const __nv_bfloat16* al = (c < 6) ? g_pl : g_t1l;
    {
        int p   = tid;
        int mat = p >> 8;
        int row = (p >> 2) & 63;
        int kq  = p & 3;
        cpa16(stage + mat * 5120 + row * 80 + kq * 16,
              (mat ? al : ah) + (m0 + row) * CH + k0 + kq * 8);
    }
    #pragma unroll
    for (int i = 0; i < 3; i++) {
        int pb  = tid + i * 512;
        int mat = pb >= 768;
        int row = (pb >> 2) % 192;
        int kq  = pb & 3;
        cpa16(stage + 10240 + mat * 15360 + row * 80 + kq * 16,
              (mat ? g_wl : g_wh) + row * 384 + c * 32 + kq * 8);
    }
}

__global__ __launch_bounds__(512, 1) void out_hmma_kernel(
    const float* __restrict__ bias, float* __restrict__ out)
{
    extern __shared__ char smem[];
    uint32_t sb = smem_u32(smem);
    float* bs = (float*)(smem + 2 * OSTG);

    int tid = threadIdx.x, lane = tid & 31, wid = tid >> 5;
    int wm = wid >> 2, wn = wid & 3;
    int m0 = blockIdx.x * 64;

    if (tid < CH) bs[tid] = bias[tid];

    float acc[6][4];
    #pragma unroll
    for (int i = 0; i < 6; i++)
        #pragma unroll
        for (int j = 0; j < 4; j++) acc[i][j] = 0.f;

    load_chunk_o(sb, m0, 0, tid);
    CP_COMMIT();

    for (int c = 0; c < 12; c++) {
        CP_WAIT0();
        __syncthreads();
        if (c < 11) {
            load_chunk_o(sb + ((c + 1) & 1) * OSTG, m0, c + 1, tid);
            CP_COMMIT();
        }
        uint32_t st = sb + (c & 1) * OSTG;
        #pragma unroll
        for (int pass = 0; pass < 3; pass++) {
            uint32_t Ab = st + (pass == 2 ? 5120u : 0u);
            uint32_t Bb = st + (pass == 1 ? 25600u : 10240u);
            #pragma unroll
            for (int ks = 0; ks < 32; ks += 16) {
                uint32_t a[4];
                {
                    uint32_t addr = Ab + (wm * 16 + (lane & 15)) * 80
                                  + (ks + ((lane >> 4) << 3)) * 2;
                    LDSM_X4(a[0], a[1], a[2], a[3], addr);
                }
                uint32_t b[6][2];
                #pragma unroll
                for (int nt2 = 0; nt2 < 3; nt2++) {
                    int qq = lane >> 3, r = lane & 7;
                    uint32_t addr = Bb
                        + (wn * 48 + nt2 * 16 + ((qq >> 1) << 3) + r) * 80
                        + (ks + ((qq & 1) << 3)) * 2;
                    LDSM_X4(b[nt2 * 2][0], b[nt2 * 2][1],
                            b[nt2 * 2 + 1][0], b[nt2 * 2 + 1][1], addr);
                }
                #pragma unroll
                for (int nt = 0; nt < 6; nt++)
                    MMA16816(acc[nt], a, b[nt]);
            }
        }
    }

    #pragma unroll
    for (int nt = 0; nt < 6; nt++) {
        int r  = m0 + wm * 16 + (lane >> 2);
        int cc = wn * 48 + nt * 8 + (lane & 3) * 2;
        float b0 = bs[cc], b1 = bs[cc + 1];
        out[r * CH + cc]           = acc[nt][0] + b0;
        out[r * CH + cc + 1]       = acc[nt][1] + b1;
        out[(r + 8) * CH + cc]     = acc[nt][2] + b0;
        out[(r + 8) * CH + cc + 1] = acc[nt][3] + b1;
    }
}

// ---------------- launch -----------------------------------------------------
extern "C" void kernel_launch(void* const* d_in, const int* in_sizes, int n_in,
                              void* d_out, int out_size) {
    const float* x    = (const float*)d_in[0];
    const float* W0   = (const float*)d_in[1];
    const float* W1   = (const float*)d_in[2];
    const float* bias = (const float*)d_in[3];
    float* out = (float*)d_out;

    static int smem_set = 0;
    if (!smem_set) {
        cudaFuncSetAttribute(knn_kernel,
                             cudaFuncAttributeMaxDynamicSharedMemorySize,
                             SMEM_TOTAL);
        cudaFuncSetAttribute(out_hmma_kernel,
                             cudaFuncAttributeMaxDynamicSharedMemorySize,
                             OSMEM);
        smem_set = 1;
    }

    transpose_kernel<<<dim3(32, 6, 8), dim3(32, 32)>>>(x);
    sqdeg_kernel<<<1024, 256>>>();
    packw_kernel<<<dim3(6, 12), dim3(32, 32)>>>(W0, W1);
    knn_kernel<<<152, 512, SMEM_TOTAL>>>();
    merge_kernel<<<256, 256>>>();
    dis_kernel<<<32, 256>>>();
    tx1_kernel<<<8192, 192>>>();
    out_hmma_kernel<<<128, 512, OSMEM>>>(bias, out);
}

// round 17
// speedup vs baseline: 1.3108x; 1.1073x over previous
#include <cuda_runtime.h>
#include <cuda_bf16.h>
#include <cstdint>

#define N_NODES 8192
#define CH      192
#define KNN     8
#define N_ITEMS 288            // 8 groups x 36 upper-triangle tiles
#define INFF __int_as_float(0x7f800000)

typedef unsigned long long ull;

// ---------------------------------------------------------------------------
// helpers (baseline PTX only: ldmatrix / mma.sync / cp.async)
// ---------------------------------------------------------------------------
__device__ __forceinline__ uint32_t smem_u32(const void* p) {
    uint32_t a;
    asm("{ .reg .u64 t; cvta.to.shared.u64 t, %1; cvt.u32.u64 %0, t; }"
        : "=r"(a) : "l"(p));
    return a;
}
__device__ __forceinline__ void cpa16(uint32_t dst, const void* src) {
    asm volatile("cp.async.cg.shared.global [%0], [%1], 16;"
                 :: "r"(dst), "l"(src) : "memory");
}
#define CP_COMMIT() asm volatile("cp.async.commit_group;" ::: "memory")
#define CP_WAIT0()  asm volatile("cp.async.wait_group 0;"  ::: "memory")
#define CP_WAIT1()  asm volatile("cp.async.wait_group 1;"  ::: "memory")

#define LDSM_X4(r0, r1, r2, r3, addr) \
    asm volatile("ldmatrix.sync.aligned.m8n8.x4.shared.b16 {%0,%1,%2,%3}, [%4];" \
        : "=r"(r0), "=r"(r1), "=r"(r2), "=r"(r3) : "r"(addr))

#define MMA16816(d, a, b) \
    asm volatile("mma.sync.aligned.m16n8k16.row.col.f32.bf16.bf16.f32 " \
        "{%0,%1,%2,%3}, {%4,%5,%6,%7}, {%8,%9}, {%0,%1,%2,%3};" \
        : "+f"((d)[0]), "+f"((d)[1]), "+f"((d)[2]), "+f"((d)[3]) \
        : "r"((a)[0]), "r"((a)[1]), "r"((a)[2]), "r"((a)[3]), \
          "r"((b)[0]), "r"((b)[1]))

// ---------------------------------------------------------------------------
// scratch (static device globals; no allocations)
// ---------------------------------------------------------------------------
__device__ float g_xf [N_NODES * CH];
__device__ float g_sq [N_NODES];
__device__ float g_dis[N_NODES];
__device__ int   g_nbr[N_NODES * KNN];
__device__ int   g_deg[N_NODES];
__device__ int   g_work;
__device__ ull   g_cand[N_NODES * 128];       // 16 lists x 8 per row

__device__ __align__(16) __nv_bfloat16 g_ph [N_NODES * CH];
__device__ __align__(16) __nv_bfloat16 g_pl [N_NODES * CH];
__device__ __align__(16) __nv_bfloat16 g_t1h[N_NODES * CH];
__device__ __align__(16) __nv_bfloat16 g_t1l[N_NODES * CH];
__device__ __align__(16) __nv_bfloat16 g_wh [CH * 384];
__device__ __align__(16) __nv_bfloat16 g_wl [CH * 384];

// ---------------- K1: NCHW -> [N, C] transpose + bf16 hi/lo pack -----------
__global__ void transpose_kernel(const float* __restrict__ x) {
    __shared__ float tile[32][33];
    int b  = blockIdx.z;
    int c0 = blockIdx.y * 32;
    int p0 = blockIdx.x * 32;
    int tx = threadIdx.x, ty = threadIdx.y;
    tile[ty][tx] = x[((b * CH) + (c0 + ty)) * 1024 + p0 + tx];
    __syncthreads();
    float v   = tile[tx][ty];
    int node  = b * 1024 + p0 + ty;
    int c     = c0 + tx;
    g_xf[node * CH + c] = v;
    __nv_bfloat16 h = __float2bfloat16(v);
    g_ph[node * CH + c] = h;
    g_pl[node * CH + c] = __float2bfloat16(v - __bfloat162float(h));
}

// ---------------- K2: squared norms + zero degree + work-counter reset ------
__global__ void sqdeg_kernel() {
    if (blockIdx.x == 0 && threadIdx.x == 0) g_work = 0;
    int q    = blockIdx.x * 8 + (threadIdx.x >> 5);
    int lane = threadIdx.x & 31;
    const float* row = g_xf + q * CH;
    float s = 0.f;
    #pragma unroll
    for (int c = lane; c < CH; c += 32) { float v = row[c]; s += v * v; }
    #pragma unroll
    for (int o = 16; o; o >>= 1) s += __shfl_xor_sync(0xffffffffu, s, o);
    if (lane == 0) { g_sq[q] = s; g_deg[q] = 0; }
}

// ---------------- K2c: pack W transposed (coalesced): g_w*[n][k] ------------
__global__ void packw_kernel(const float* __restrict__ W0,
                             const float* __restrict__ W1) {
    __shared__ float t[32][33];
    int n0 = blockIdx.x * 32;
    int k0 = blockIdx.y * 32;
    int tx = threadIdx.x, ty = threadIdx.y;
    int k  = k0 + ty, n = n0 + tx;
    t[ty][tx] = (k < CH) ? W0[k * CH + n] : W1[(k - CH) * CH + n];
    __syncthreads();
    float v = t[tx][ty];
    __nv_bfloat16 h = __float2bfloat16(v);
    g_wh[(n0 + ty) * 384 + k0 + tx] = h;
    g_wl[(n0 + ty) * 384 + k0 + tx] = __float2bfloat16(v - __bfloat162float(h));
}

// ---------------- K3: persistent fused HMMA d2 + symmetric top-8 -----------
// d2s stride 132 floats: rows 16B-aligned for float4 scans, cols conflict-free
#define D2S 132
#define OFF_MISC 0
#define OFF_SQ   128                         // sqs[2][1024]
#define OFF_D2   (OFF_SQ + 8192)             // 128 x 132 floats
#define OFF_STG  (OFF_D2 + 128 * D2S * 4)
#define STG_SZ   40960                       // Ah|Al|Bh|Bl, 128 rows x 80B each
#define SMEM_TOTAL (OFF_STG + 3 * STG_SZ)    // 198784

__device__ __forceinline__ void decode_item(int w, int& g, int& I, int& J) {
    g = w / 36;
    int r = w - g * 36;
    int i = 0, span = 8;
    while (r >= span) { r -= span; span--; i++; }
    I = i; J = i + r;
}

__device__ __forceinline__ void load_chunk(uint32_t stage, int Arow0, int Brow0,
                                           int k0, int tid) {
    #pragma unroll
    for (int i = 0; i < 4; i++) {
        int p   = tid + i * 512;
        int mat = p >> 9;                    // 0:Ah 1:Al 2:Bh 3:Bl
        int row = (p >> 2) & 127;
        int kq  = p & 3;
        const __nv_bfloat16* base = (mat & 1) ? g_pl : g_ph;
        int node = ((mat < 2) ? Arow0 : Brow0) + row;
        cpa16(stage + mat * 10240 + row * 80 + kq * 16,
              base + node * CH + k0 + kq * 8);
    }
}

__device__ __forceinline__ void top8_insert(float d2, int n, float* v, int* id8) {
    if (d2 < v[7]) {
        v[7] = d2; id8[7] = n;
        #pragma unroll
        for (int s = 7; s > 0; s--) {
            if (v[s] < v[s - 1]) {
                float tv = v[s]; v[s] = v[s - 1]; v[s - 1] = tv;
                int   ti = id8[s]; id8[s] = id8[s - 1]; id8[s - 1] = ti;
            }
        }
    }
}

__global__ __launch_bounds__(512, 1) void knn_kernel() {
    extern __shared__ char smem[];
    uint32_t sb = smem_u32(smem);
    int*   misc = (int*)smem;
    float* sqsA = (float*)(smem + OFF_SQ);
    float* d2s  = (float*)(smem + OFF_D2);

    int tid = threadIdx.x, lane = tid & 31, wid = tid >> 5;
    int wm = wid >> 2, wn = wid & 3;        // 4 x 4 warp grid, 32x32 per warp

    if (tid == 0) misc[0] = atomicAdd(&g_work, 1);
    __syncthreads();
    int w = misc[0];
    int g, I, J;
    decode_item(w, g, I, J);
    int gStart = g << 10;
    int gSize  = (g == 7) ? 1023 : 1024;
    int A0 = gStart + I * 128, B0 = gStart + J * 128;
    int sqbuf = 0;

    for (int i = tid; i < 1024; i += 512) sqsA[i] = g_sq[gStart + i];
    load_chunk(sb + OFF_STG, A0, B0, 0, tid);  CP_COMMIT();
    load_chunk(sb + OFF_STG + STG_SZ, A0, B0, 32, tid);  CP_COMMIT();
    __syncthreads();

    while (w < N_ITEMS) {
        float* sqs = sqsA + sqbuf * 1024;
        float acc[8][4];
        #pragma unroll
        for (int i = 0; i < 8; i++)
            #pragma unroll
            for (int j = 0; j < 4; j++) acc[i][j] = 0.f;

        int wNext = 0x7fffffff;
        int gN = 0, IN_ = 0, JN = 0, A0n = 0, B0n = 0, gStartN = 0;

        for (int c = 0; c < 6; c++) {
            if (c == 5 && wNext >= N_ITEMS) { CP_WAIT0(); } else { CP_WAIT1(); }
            __syncthreads();
            if (c <= 3) {
                load_chunk(sb + OFF_STG + ((c + 2) % 3) * STG_SZ, A0, B0,
                           (c + 2) * 32, tid);
                CP_COMMIT();
            }
            if (c == 3 && tid == 0) misc[1] = atomicAdd(&g_work, 1);
            if (c == 4) {
                wNext = misc[1];
                if (wNext < N_ITEMS) {
                    decode_item(wNext, gN, IN_, JN);
                    gStartN = gN << 10;
                    A0n = gStartN + IN_ * 128; B0n = gStartN + JN * 128;
                    load_chunk(sb + OFF_STG, A0n, B0n, 0, tid);
                    CP_COMMIT();
                }
            }
            uint32_t st = sb + OFF_STG + (c % 3) * STG_SZ;
            // split passes with operand reuse: 8 LDSM_X4 per ks (was 12)
            #pragma unroll
            for (int ks = 0; ks < 32; ks += 16) {
                uint32_t aoffB = (wm * 32 + (lane & 15)) * 80
                               + (ks + ((lane >> 4) << 3)) * 2;
                int qq = lane >> 3, rr = lane & 7;
                uint32_t boffB = (wn * 32 + ((qq >> 1) << 3) + rr) * 80
                               + (ks + ((qq & 1) << 3)) * 2;

                uint32_t ah[2][4], al[2][4], bh[4][2], bl[4][2];
                #pragma unroll
                for (int mt = 0; mt < 2; mt++)
                    LDSM_X4(ah[mt][0], ah[mt][1], ah[mt][2], ah[mt][3],
                            st + aoffB + mt * (16 * 80));
                #pragma unroll
                for (int nt2 = 0; nt2 < 2; nt2++)
                    LDSM_X4(bh[nt2 * 2][0], bh[nt2 * 2][1],
                            bh[nt2 * 2 + 1][0], bh[nt2 * 2 + 1][1],
                            st + 20480u + boffB + nt2 * (16 * 80));
                #pragma unroll
                for (int mt = 0; mt < 2; mt++)           // hh
                    #pragma unroll
                    for (int nt = 0; nt < 4; nt++)
                        MMA16816(acc[mt * 4 + nt], ah[mt], bh[nt]);

                #pragma unroll
                for (int mt = 0; mt < 2; mt++)
                    LDSM_X4(al[mt][0], al[mt][1], al[mt][2], al[mt][3],
                            st + 10240u + aoffB + mt * (16 * 80));
                #pragma unroll
                for (int mt = 0; mt < 2; mt++)           // lh (Bh reused)
                    #pragma unroll
                    for (int nt = 0; nt < 4; nt++)
                        MMA16816(acc[mt * 4 + nt], al[mt], bh[nt]);

                #pragma unroll
                for (int nt2 = 0; nt2 < 2; nt2++)
                    LDSM_X4(bl[nt2 * 2][0], bl[nt2 * 2][1],
                            bl[nt2 * 2 + 1][0], bl[nt2 * 2 + 1][1],
                            st + 30720u + boffB + nt2 * (16 * 80));
                #pragma unroll
                for (int mt = 0; mt < 2; mt++)           // hl (Ah reused)
                    #pragma unroll
                    for (int nt = 0; nt < 4; nt++)
                        MMA16816(acc[mt * 4 + nt], ah[mt], bl[nt]);
            }
        }

        // epilogue: dot -> smem tile
        #pragma unroll
        for (int mt = 0; mt < 2; mt++)
            #pragma unroll
            for (int nt = 0; nt < 4; nt++) {
                int r0 = wm * 32 + mt * 16 + (lane >> 2);
                int c0 = wn * 32 + nt * 8 + (lane & 3) * 2;
                float* p = d2s + r0 * D2S + c0;
                p[0]           = acc[mt * 4 + nt][0];
                p[1]           = acc[mt * 4 + nt][1];
                p[D2S * 8]     = acc[mt * 4 + nt][2];
                p[D2S * 8 + 1] = acc[mt * 4 + nt][3];
            }
        bool hasNext = (wNext < N_ITEMS);
        if (hasNext) {
            load_chunk(sb + OFF_STG + STG_SZ, A0n, B0n, 32, tid);
            if (tid < 256)
                cpa16(sb + OFF_SQ + (sqbuf ^ 1) * 4096 + tid * 16,
                      g_sq + gStartN + tid * 4);
            CP_COMMIT();
        }
        __syncthreads();

        // scans run CONCURRENTLY: threads 0-255 row scan (float4), 256-511 col
        if (tid < 256) {
            int   row  = tid & 127;
            int   half = tid >> 7;
            int   mLoc = I * 128 + row;
            float sqm  = sqs[mLoc];
            float v[8]; int id8[8];
            #pragma unroll
            for (int s = 0; s < 8; s++) { v[s] = INFF; id8[s] = 1 << 30; }
            const float4* rp4 = (const float4*)(d2s + row * D2S + half * 64);
            const float4* sq4 = (const float4*)(sqs + J * 128 + half * 64);
            int nb0 = J * 128 + half * 64;
            #pragma unroll 4
            for (int c4 = 0; c4 < 16; c4++) {
                float4 dv = rp4[c4];
                float4 sv = sq4[c4];
                int n = nb0 + c4 * 4;
                float d2;
                d2 = fmaf(-2.f, dv.x, sqm + sv.x);
                if (n < gSize && n != mLoc) top8_insert(d2, n, v, id8);
                d2 = fmaf(-2.f, dv.y, sqm + sv.y);
                if (n + 1 < gSize && n + 1 != mLoc) top8_insert(d2, n + 1, v, id8);
                d2 = fmaf(-2.f, dv.z, sqm + sv.z);
                if (n + 2 < gSize && n + 2 != mLoc) top8_insert(d2, n + 2, v, id8);
                d2 = fmaf(-2.f, dv.w, sqm + sv.w);
                if (n + 3 < gSize && n + 3 != mLoc) top8_insert(d2, n + 3, v, id8);
            }
            int q = gStart + mLoc;
            ull* cd = g_cand + (size_t)q * 128 + J * 16 + half * 8;
            #pragma unroll
            for (int r = 0; r < KNN; r++)
                cd[r] = ((ull)__float_as_uint(v[r]) << 32)
                      | (unsigned)(gStart + id8[r]);
        } else if (I != J) {
            int   t2   = tid - 256;
            int   row  = t2 & 127;
            int   half = t2 >> 7;
            int   nLoc = J * 128 + row;
            float sqn  = sqs[nLoc];
            float v[8]; int id8[8];
            #pragma unroll
            for (int s = 0; s < 8; s++) { v[s] = INFF; id8[s] = 1 << 30; }
            int mb0 = I * 128 + half * 64;
            const float* cp = d2s + (half * 64) * D2S + row;
            #pragma unroll 4
            for (int c = 0; c < 64; c++) {
                int   m   = mb0 + c;
                float d2  = fmaf(-2.f, cp[c * D2S], sqn + sqs[m]);
                if (m < gSize) top8_insert(d2, m, v, id8);
            }
            int q = gStart + nLoc;
            ull* cd = g_cand + (size_t)q * 128 + I * 16 + half * 8;
            #pragma unroll
            for (int r = 0; r < KNN; r++)
                cd[r] = ((ull)__float_as_uint(v[r]) << 32)
                      | (unsigned)(gStart + id8[r]);
        }
        __syncthreads();

        w = wNext; g = gN; I = IN_; J = JN;
        gStart = gStartN; gSize = (g == 7) ? 1023 : 1024;
        A0 = A0n; B0 = B0n; sqbuf ^= 1;
    }
}

// ---------------- K4: merge 16 partial lists per row (R6 exact) -------------
__global__ void merge_kernel() {
    int q    = (blockIdx.x * 256 + threadIdx.x) >> 5;
    int lane = threadIdx.x & 31;
    if (q == N_NODES - 1) {
        if (lane < KNN) g_nbr[q * KNN + lane] = 0;
        return;
    }
    const ull* cd = g_cand + (size_t)q * 128;
    ull k0 = cd[lane], k1 = cd[32 + lane],
        k2 = cd[64 + lane], k3 = cd[96 + lane];
    #define CSWP(a, b) if (b < a) { ull t = a; a = b; b = t; }
    CSWP(k0, k1); CSWP(k2, k3); CSWP(k0, k2); CSWP(k1, k3); CSWP(k1, k2);
    #undef CSWP

    #pragma unroll
    for (int r = 0; r < KNN; r++) {
        ull m = k0;
        #pragma unroll
        for (int o = 16; o; o >>= 1) {
            ull other = __shfl_xor_sync(0xffffffffu, m, o);
            m = (other < m) ? other : m;
        }
        if (k0 == m) {
            int nb = (int)(m & 0xffffffffu);
            g_nbr[q * KNN + r] = nb;
            atomicAdd(&g_deg[nb], 1);
            k0 = k1; k1 = k2; k2 = k3; k3 = 0xFFFFFFFFFFFFFFFFull;
        }
    }
}

// ---------------- K5: dis = deg^{-1/2} --------------------------------------
__global__ void dis_kernel() {
    int i = blockIdx.x * 256 + threadIdx.x;
    if (i < N_NODES) {
        int d = g_deg[i];
        g_dis[i] = (d > 0) ? rsqrtf((float)d) : 0.0f;
    }
}

// ---------------- K6: Tx1 -> bf16 hi/lo --------------------------------------
__global__ void tx1_kernel() {
    int q = blockIdx.x;
    int c = threadIdx.x;
    float dq = g_dis[q];
    float s = 0.f;
    #pragma unroll
    for (int e = 0; e < KNN; e++) {
        int j = g_nbr[q * KNN + e];
        s += g_dis[j] * g_xf[j * CH + c];
    }
    float t1 = -dq * s;
    __nv_bfloat16 h = __float2bfloat16(t1);
    g_t1h[q * CH + c] = h;
    g_t1l[q * CH + c] = __float2bfloat16(t1 - __bfloat162float(h));
}

// ---------------- K7: HMMA out = [xf|tx1] @ [W0;W1] + bias -------------------
#define OSTG 40960
#define OSMEM (2 * OSTG + 768)

__device__ __forceinline__ void load_chunk_o(uint32_t stage, int m0, int c, int tid) {
    int k0 = (c < 6 ? c : c - 6) * 32;
    const __nv_bfloat16* ah = (c < 6) ? g_ph : g_t1h;
    const __nv_bfloat16* al = (c < 6) ? g_pl : g_t1l;
    {
        int p   = tid;
        int mat = p >> 8;
        int row = (p >> 2) & 63;
        int kq  = p & 3;
        cpa16(stage + mat * 5120 + row * 80 + kq * 16,
              (mat ? al : ah) + (m0 + row) * CH + k0 + kq * 8);
    }
    #pragma unroll
    for (int i = 0; i < 3; i++) {
        int pb  = tid + i * 512;
        int mat = pb >= 768;
        int row = (pb >> 2) % 192;
        int kq  = pb & 3;
        cpa16(stage + 10240 + mat * 15360 + row * 80 + kq * 16,
              (mat ? g_wl : g_wh) + row * 384 + c * 32 + kq * 8);
    }
}

__global__ __launch_bounds__(512, 1) void out_hmma_kernel(
    const float* __restrict__ bias, float* __restrict__ out)
{
    extern __shared__ char smem[];
    uint32_t sb = smem_u32(smem);
    float* bs = (float*)(smem + 2 * OSTG);

    int tid = threadIdx.x, lane = tid & 31, wid = tid >> 5;
    int wm = wid >> 2, wn = wid & 3;
    int m0 = blockIdx.x * 64;

    if (tid < CH) bs[tid] = bias[tid];

    float acc[6][4];
    #pragma unroll
    for (int i = 0; i < 6; i++)
        #pragma unroll
        for (int j = 0; j < 4; j++) acc[i][j] = 0.f;

    load_chunk_o(sb, m0, 0, tid);
    CP_COMMIT();

    for (int c = 0; c < 12; c++) {
        CP_WAIT0();
        __syncthreads();
        if (c < 11) {
            load_chunk_o(sb + ((c + 1) & 1) * OSTG, m0, c + 1, tid);
            CP_COMMIT();
        }
        uint32_t st = sb + (c & 1) * OSTG;
        #pragma unroll
        for (int pass = 0; pass < 3; pass++) {
            uint32_t Ab = st + (pass == 2 ? 5120u : 0u);
            uint32_t Bb = st + (pass == 1 ? 25600u : 10240u);
            #pragma unroll
            for (int ks = 0; ks < 32; ks += 16) {
                uint32_t a[4];
                {
                    uint32_t addr = Ab + (wm * 16 + (lane & 15)) * 80
                                  + (ks + ((lane >> 4) << 3)) * 2;
                    LDSM_X4(a[0], a[1], a[2], a[3], addr);
                }
                uint32_t b[6][2];
                #pragma unroll
                for (int nt2 = 0; nt2 < 3; nt2++) {
                    int qq = lane >> 3, r = lane & 7;
                    uint32_t addr = Bb
                        + (wn * 48 + nt2 * 16 + ((qq >> 1) << 3) + r) * 80
                        + (ks + ((qq & 1) << 3)) * 2;
                    LDSM_X4(b[nt2 * 2][0], b[nt2 * 2][1],
                            b[nt2 * 2 + 1][0], b[nt2 * 2 + 1][1], addr);
                }
                #pragma unroll
                for (int nt = 0; nt < 6; nt++)
                    MMA16816(acc[nt], a, b[nt]);
            }
        }
    }

    #pragma unroll
    for (int nt = 0; nt < 6; nt++) {
        int r  = m0 + wm * 16 + (lane >> 2);
        int cc = wn * 48 + nt * 8 + (lane & 3) * 2;
        float b0 = bs[cc], b1 = bs[cc + 1];
        out[r * CH + cc]           = acc[nt][0] + b0;
        out[r * CH + cc + 1]       = acc[nt][1] + b1;
        out[(r + 8) * CH + cc]     = acc[nt][2] + b0;
        out[(r + 8) * CH + cc + 1] = acc[nt][3] + b1;
    }
}

// ---------------- launch -----------------------------------------------------
extern "C" void kernel_launch(void* const* d_in, const int* in_sizes, int n_in,
                              void* d_out, int out_size) {
    const float* x    = (const float*)d_in[0];
    const float* W0   = (const float*)d_in[1];
    const float* W1   = (const float*)d_in[2];
    const float* bias = (const float*)d_in[3];
    float* out = (float*)d_out;

    static int smem_set = 0;
    if (!smem_set) {
        cudaFuncSetAttribute(knn_kernel,
                             cudaFuncAttributeMaxDynamicSharedMemorySize,
                             SMEM_TOTAL);
        cudaFuncSetAttribute(out_hmma_kernel,
                             cudaFuncAttributeMaxDynamicSharedMemorySize,
                             OSMEM);
        smem_set = 1;
    }

    transpose_kernel<<<dim3(32, 6, 8), dim3(32, 32)>>>(x);
    sqdeg_kernel<<<1024, 256>>>();
    packw_kernel<<<dim3(6, 12), dim3(32, 32)>>>(W0, W1);
    knn_kernel<<<152, 512, SMEM_TOTAL>>>();
    merge_kernel<<<1024, 256>>>();
    dis_kernel<<<32, 256>>>();
    tx1_kernel<<<8192, 192>>>();
    out_hmma_kernel<<<128, 512, OSMEM>>>(bias, out);
}